// round 13
// baseline (speedup 1.0000x reference)
#include <cuda_runtime.h>

// NonMaximaSuppression2d: out = x * (x > max over 3x3 neighborhood excluding
// center), replicate padding. (8,4,2048,2048) fp32. HBM-bound stream.
//
// FINAL (R8, re-certified twice at 156.1us; ncu kernel time 151.2us).
//  - 8 output rows/thread in two phase-separated 4-row chunks: all 6 (then 4)
//    row LDG.128s issued back-to-back before any consumer -> MLP=6/4 covers
//    DRAM latency (the single biggest win: 185 -> 164us in R2).
//  - warp-shuffle x-halos; scalar halo loads only on lanes 0/31 (L1/L2 hits).
//  - interior CTAs (510/512 strips) take a no-clamp path: one base pointer,
//    row offsets folded into LDG/STG [R+imm] via compile-time W=2048.
//  - __stcs evict-first stores: output is never re-read, keep L2 for halos.
// At the chip's 1R:1W streaming ceiling: 6.74 TB/s (85% of spec), traffic at
// the algorithmic minimum. Falsified alternatives: 256-bit ld/st (R9),
// TPB=256 (R10), RPT=16 (R11), fused load+shuffle (R6), asm .cs stores (R3).

#define TPB 128          // 128 threads * float4 = 512 px per block in x
#define RPT 8            // output rows per thread (two 4-row chunks)
#define HH  2048
#define WW  2048

__device__ __forceinline__ float max3(float a, float b, float c) {
    return fmaxf(fmaxf(a, b), c);
}

// Halo extraction for one loaded row (shuffles + predicated edge loads).
template <bool CLAMP>
__device__ __forceinline__ void
halo_row(const float* __restrict__ p, int x4, int yy, int lane,
         const float4& v, float& lh, float& rh) {
    float fl = __shfl_up_sync(0xffffffffu, v.w, 1);
    float fr = __shfl_down_sync(0xffffffffu, v.x, 1);
    if (lane == 0 || lane == 31) {
        const int y = CLAMP ? min(max(yy, 0), HH - 1) : yy;
        const float* row = p + ((size_t)y << 11);
        if (lane == 0)  fl = (x4 > 0)      ? __ldg(row + x4 - 1) : v.x;
        if (lane == 31) fr = (x4 + 4 < WW) ? __ldg(row + x4 + 4) : v.w;
    }
    lh = fl; rh = fr;
}

// Compute+store 4 output rows from a 6-row window; qb = &out[ybase][x4].
__device__ __forceinline__ void
compute4(const float4 v[6], const float lh[6], const float rh[6],
         float* __restrict__ qb) {
    #pragma unroll
    for (int r = 0; r < 4; r++) {
        const int t = r, m = r + 1, b = r + 2;

        float t0 = max3(lh[t], v[t].x, v[t].y);
        float t1 = max3(v[t].x, v[t].y, v[t].z);
        float t2 = max3(v[t].y, v[t].z, v[t].w);
        float t3 = max3(v[t].z, v[t].w, rh[t]);

        float b0 = max3(lh[b], v[b].x, v[b].y);
        float b1 = max3(v[b].x, v[b].y, v[b].z);
        float b2 = max3(v[b].y, v[b].z, v[b].w);
        float b3 = max3(v[b].z, v[b].w, rh[b]);

        float n0 = fmaxf(lh[m],  v[m].y);
        float n1 = fmaxf(v[m].x, v[m].z);
        float n2 = fmaxf(v[m].y, v[m].w);
        float n3 = fmaxf(v[m].z, rh[m]);

        float4 o;
        float nb;
        nb = fmaxf(fmaxf(t0, b0), n0); o.x = (v[m].x > nb) ? v[m].x : 0.0f;
        nb = fmaxf(fmaxf(t1, b1), n1); o.y = (v[m].y > nb) ? v[m].y : 0.0f;
        nb = fmaxf(fmaxf(t2, b2), n2); o.z = (v[m].z > nb) ? v[m].z : 0.0f;
        nb = fmaxf(fmaxf(t3, b3), n3); o.w = (v[m].w > nb) ? v[m].w : 0.0f;

        __stcs(reinterpret_cast<float4*>(qb + r * WW), o);   // STG [R+imm]
    }
}

template <bool CLAMP>
__device__ __forceinline__ float4
load4(const float* __restrict__ p, int x4, int yy) {
    const int y = CLAMP ? min(max(yy, 0), HH - 1) : yy;
    return *reinterpret_cast<const float4*>(p + ((size_t)y << 11) + x4);
}

template <bool CLAMP>
__device__ __forceinline__ void
nms_tile(const float* __restrict__ p, float* __restrict__ q,
         int x4, int y0, int lane) {
    float4 v[6];
    float lh[6], rh[6];

    // ---- Chunk A: batch-load rows y0-1 .. y0+4 (6 independent LDG.128) ----
    #pragma unroll
    for (int j = 0; j < 6; j++)
        v[j] = load4<CLAMP>(p, x4, y0 + j - 1);
    #pragma unroll
    for (int j = 0; j < 6; j++)
        halo_row<CLAMP>(p, x4, y0 + j - 1, lane, v[j], lh[j], rh[j]);
    float* qb = q + ((size_t)y0 << 11) + x4;
    compute4(v, lh, rh, qb);

    // ---- Shift window down 4: keep rows y0+3, y0+4 ----
    v[0] = v[4];  lh[0] = lh[4];  rh[0] = rh[4];
    v[1] = v[5];  lh[1] = lh[5];  rh[1] = rh[5];

    // ---- Chunk B: batch-load rows y0+5 .. y0+8 (4 independent LDG.128) ----
    #pragma unroll
    for (int j = 2; j < 6; j++)
        v[j] = load4<CLAMP>(p, x4, y0 + j + 3);
    #pragma unroll
    for (int j = 2; j < 6; j++)
        halo_row<CLAMP>(p, x4, y0 + j + 3, lane, v[j], lh[j], rh[j]);
    compute4(v, lh, rh, qb + 4 * WW);
}

__global__ void __launch_bounds__(TPB)
nms2d_kernel(const float* __restrict__ x, float* __restrict__ out) {
    const int img = blockIdx.z;
    const size_t base = (size_t)img * HH * WW;
    const float* __restrict__ p = x + base;
    float* __restrict__ q = out + base;

    const int lane = threadIdx.x & 31;
    const int x4 = (blockIdx.x * TPB + threadIdx.x) * 4;
    const int y0 = blockIdx.y * RPT;

    if (y0 > 0 && y0 + RPT < HH) {
        nms_tile<false>(p, q, x4, y0, lane);   // interior: no y clamps
    } else {
        nms_tile<true>(p, q, x4, y0, lane);    // top/bottom edge strips
    }
}

extern "C" void kernel_launch(void* const* d_in, const int* in_sizes, int n_in,
                              void* d_out, int out_size) {
    const float* x = (const float*)d_in[0];
    float* out = (float*)d_out;

    const int n_img = in_sizes[0] / (HH * WW);   // 32

    dim3 block(TPB, 1, 1);
    dim3 grid(WW / (TPB * 4), HH / RPT, n_img);
    nms2d_kernel<<<grid, block>>>(x, out);
}

// round 14
// speedup vs baseline: 1.0062x; 1.0062x over previous
#include <cuda_runtime.h>

// NonMaximaSuppression2d: out = x * (x > max over 3x3 neighborhood excluding
// center), replicate padding. (8,4,2048,2048) fp32. HBM-bound stream.
//
// R14 = R8 (best: 156.1us, re-certified twice) + ONE isolated change:
// __stwt write-through stores instead of __stcs evict-first. Completes the
// store-policy matrix (default/.cs/.wt); .wt skips L2 write-allocate for
// the never-re-read output. Everything else identical to R8.

#define TPB 128          // 128 threads * float4 = 512 px per block in x
#define RPT 8            // output rows per thread (two 4-row chunks)
#define HH  2048
#define WW  2048

__device__ __forceinline__ float max3(float a, float b, float c) {
    return fmaxf(fmaxf(a, b), c);
}

// Halo extraction for one loaded row (shuffles + predicated edge loads).
template <bool CLAMP>
__device__ __forceinline__ void
halo_row(const float* __restrict__ p, int x4, int yy, int lane,
         const float4& v, float& lh, float& rh) {
    float fl = __shfl_up_sync(0xffffffffu, v.w, 1);
    float fr = __shfl_down_sync(0xffffffffu, v.x, 1);
    if (lane == 0 || lane == 31) {
        const int y = CLAMP ? min(max(yy, 0), HH - 1) : yy;
        const float* row = p + ((size_t)y << 11);
        if (lane == 0)  fl = (x4 > 0)      ? __ldg(row + x4 - 1) : v.x;
        if (lane == 31) fr = (x4 + 4 < WW) ? __ldg(row + x4 + 4) : v.w;
    }
    lh = fl; rh = fr;
}

// Compute+store 4 output rows from a 6-row window; qb = &out[ybase][x4].
__device__ __forceinline__ void
compute4(const float4 v[6], const float lh[6], const float rh[6],
         float* __restrict__ qb) {
    #pragma unroll
    for (int r = 0; r < 4; r++) {
        const int t = r, m = r + 1, b = r + 2;

        float t0 = max3(lh[t], v[t].x, v[t].y);
        float t1 = max3(v[t].x, v[t].y, v[t].z);
        float t2 = max3(v[t].y, v[t].z, v[t].w);
        float t3 = max3(v[t].z, v[t].w, rh[t]);

        float b0 = max3(lh[b], v[b].x, v[b].y);
        float b1 = max3(v[b].x, v[b].y, v[b].z);
        float b2 = max3(v[b].y, v[b].z, v[b].w);
        float b3 = max3(v[b].z, v[b].w, rh[b]);

        float n0 = fmaxf(lh[m],  v[m].y);
        float n1 = fmaxf(v[m].x, v[m].z);
        float n2 = fmaxf(v[m].y, v[m].w);
        float n3 = fmaxf(v[m].z, rh[m]);

        float4 o;
        float nb;
        nb = fmaxf(fmaxf(t0, b0), n0); o.x = (v[m].x > nb) ? v[m].x : 0.0f;
        nb = fmaxf(fmaxf(t1, b1), n1); o.y = (v[m].y > nb) ? v[m].y : 0.0f;
        nb = fmaxf(fmaxf(t2, b2), n2); o.z = (v[m].z > nb) ? v[m].z : 0.0f;
        nb = fmaxf(fmaxf(t3, b3), n3); o.w = (v[m].w > nb) ? v[m].w : 0.0f;

        __stwt(reinterpret_cast<float4*>(qb + r * WW), o);   // write-through
    }
}

template <bool CLAMP>
__device__ __forceinline__ float4
load4(const float* __restrict__ p, int x4, int yy) {
    const int y = CLAMP ? min(max(yy, 0), HH - 1) : yy;
    return *reinterpret_cast<const float4*>(p + ((size_t)y << 11) + x4);
}

template <bool CLAMP>
__device__ __forceinline__ void
nms_tile(const float* __restrict__ p, float* __restrict__ q,
         int x4, int y0, int lane) {
    float4 v[6];
    float lh[6], rh[6];

    // ---- Chunk A: batch-load rows y0-1 .. y0+4 (6 independent LDG.128) ----
    #pragma unroll
    for (int j = 0; j < 6; j++)
        v[j] = load4<CLAMP>(p, x4, y0 + j - 1);
    #pragma unroll
    for (int j = 0; j < 6; j++)
        halo_row<CLAMP>(p, x4, y0 + j - 1, lane, v[j], lh[j], rh[j]);
    float* qb = q + ((size_t)y0 << 11) + x4;
    compute4(v, lh, rh, qb);

    // ---- Shift window down 4: keep rows y0+3, y0+4 ----
    v[0] = v[4];  lh[0] = lh[4];  rh[0] = rh[4];
    v[1] = v[5];  lh[1] = lh[5];  rh[1] = rh[5];

    // ---- Chunk B: batch-load rows y0+5 .. y0+8 (4 independent LDG.128) ----
    #pragma unroll
    for (int j = 2; j < 6; j++)
        v[j] = load4<CLAMP>(p, x4, y0 + j + 3);
    #pragma unroll
    for (int j = 2; j < 6; j++)
        halo_row<CLAMP>(p, x4, y0 + j + 3, lane, v[j], lh[j], rh[j]);
    compute4(v, lh, rh, qb + 4 * WW);
}

__global__ void __launch_bounds__(TPB)
nms2d_kernel(const float* __restrict__ x, float* __restrict__ out) {
    const int img = blockIdx.z;
    const size_t base = (size_t)img * HH * WW;
    const float* __restrict__ p = x + base;
    float* __restrict__ q = out + base;

    const int lane = threadIdx.x & 31;
    const int x4 = (blockIdx.x * TPB + threadIdx.x) * 4;
    const int y0 = blockIdx.y * RPT;

    if (y0 > 0 && y0 + RPT < HH) {
        nms_tile<false>(p, q, x4, y0, lane);   // interior: no y clamps
    } else {
        nms_tile<true>(p, q, x4, y0, lane);    // top/bottom edge strips
    }
}

extern "C" void kernel_launch(void* const* d_in, const int* in_sizes, int n_in,
                              void* d_out, int out_size) {
    const float* x = (const float*)d_in[0];
    float* out = (float*)d_out;

    const int n_img = in_sizes[0] / (HH * WW);   // 32

    dim3 block(TPB, 1, 1);
    dim3 grid(WW / (TPB * 4), HH / RPT, n_img);
    nms2d_kernel<<<grid, block>>>(x, out);
}

// round 15
// speedup vs baseline: 1.0074x; 1.0012x over previous
#include <cuda_runtime.h>

// NonMaximaSuppression2d: out = x * (x > max over 3x3 neighborhood excluding
// center), replicate padding. (8,4,2048,2048) fp32. HBM-bound stream.
//
// FINAL (R14, best: 155.7us wall / 151.3us kernel, DRAM=85.5%, 6.78 TB/s).
//  - 8 output rows/thread in two phase-separated 4-row chunks: all 6 (then 4)
//    row LDG.128s issued back-to-back before any consumer -> MLP=6/4 covers
//    DRAM latency (the single biggest win of the session: 185 -> 164us).
//  - warp-shuffle x-halos; scalar halo loads only on lanes 0/31 (L1/L2 hits).
//  - interior CTAs (510/512 strips) take a no-clamp path: one base pointer,
//    row offsets folded into LDG/STG [R+imm] via compile-time W=2048.
//  - __stwt write-through stores: output is never re-read; skipping L2
//    write-allocate entirely beat both default and .cs evict-first.
// Traffic at the algorithmic minimum; bandwidth at the chip's demonstrated
// 1R:1W streaming ceiling. Falsified: 256-bit ld/st, TPB=256, RPT=16,
// fused load+shuffle, asm .cs stores, pointer-array addressing.

#define TPB 128          // 128 threads * float4 = 512 px per block in x
#define RPT 8            // output rows per thread (two 4-row chunks)
#define HH  2048
#define WW  2048

__device__ __forceinline__ float max3(float a, float b, float c) {
    return fmaxf(fmaxf(a, b), c);
}

// Halo extraction for one loaded row (shuffles + predicated edge loads).
template <bool CLAMP>
__device__ __forceinline__ void
halo_row(const float* __restrict__ p, int x4, int yy, int lane,
         const float4& v, float& lh, float& rh) {
    float fl = __shfl_up_sync(0xffffffffu, v.w, 1);
    float fr = __shfl_down_sync(0xffffffffu, v.x, 1);
    if (lane == 0 || lane == 31) {
        const int y = CLAMP ? min(max(yy, 0), HH - 1) : yy;
        const float* row = p + ((size_t)y << 11);
        if (lane == 0)  fl = (x4 > 0)      ? __ldg(row + x4 - 1) : v.x;
        if (lane == 31) fr = (x4 + 4 < WW) ? __ldg(row + x4 + 4) : v.w;
    }
    lh = fl; rh = fr;
}

// Compute+store 4 output rows from a 6-row window; qb = &out[ybase][x4].
__device__ __forceinline__ void
compute4(const float4 v[6], const float lh[6], const float rh[6],
         float* __restrict__ qb) {
    #pragma unroll
    for (int r = 0; r < 4; r++) {
        const int t = r, m = r + 1, b = r + 2;

        float t0 = max3(lh[t], v[t].x, v[t].y);
        float t1 = max3(v[t].x, v[t].y, v[t].z);
        float t2 = max3(v[t].y, v[t].z, v[t].w);
        float t3 = max3(v[t].z, v[t].w, rh[t]);

        float b0 = max3(lh[b], v[b].x, v[b].y);
        float b1 = max3(v[b].x, v[b].y, v[b].z);
        float b2 = max3(v[b].y, v[b].z, v[b].w);
        float b3 = max3(v[b].z, v[b].w, rh[b]);

        float n0 = fmaxf(lh[m],  v[m].y);
        float n1 = fmaxf(v[m].x, v[m].z);
        float n2 = fmaxf(v[m].y, v[m].w);
        float n3 = fmaxf(v[m].z, rh[m]);

        float4 o;
        float nb;
        nb = fmaxf(fmaxf(t0, b0), n0); o.x = (v[m].x > nb) ? v[m].x : 0.0f;
        nb = fmaxf(fmaxf(t1, b1), n1); o.y = (v[m].y > nb) ? v[m].y : 0.0f;
        nb = fmaxf(fmaxf(t2, b2), n2); o.z = (v[m].z > nb) ? v[m].z : 0.0f;
        nb = fmaxf(fmaxf(t3, b3), n3); o.w = (v[m].w > nb) ? v[m].w : 0.0f;

        __stwt(reinterpret_cast<float4*>(qb + r * WW), o);   // write-through
    }
}

template <bool CLAMP>
__device__ __forceinline__ float4
load4(const float* __restrict__ p, int x4, int yy) {
    const int y = CLAMP ? min(max(yy, 0), HH - 1) : yy;
    return *reinterpret_cast<const float4*>(p + ((size_t)y << 11) + x4);
}

template <bool CLAMP>
__device__ __forceinline__ void
nms_tile(const float* __restrict__ p, float* __restrict__ q,
         int x4, int y0, int lane) {
    float4 v[6];
    float lh[6], rh[6];

    // ---- Chunk A: batch-load rows y0-1 .. y0+4 (6 independent LDG.128) ----
    #pragma unroll
    for (int j = 0; j < 6; j++)
        v[j] = load4<CLAMP>(p, x4, y0 + j - 1);
    #pragma unroll
    for (int j = 0; j < 6; j++)
        halo_row<CLAMP>(p, x4, y0 + j - 1, lane, v[j], lh[j], rh[j]);
    float* qb = q + ((size_t)y0 << 11) + x4;
    compute4(v, lh, rh, qb);

    // ---- Shift window down 4: keep rows y0+3, y0+4 ----
    v[0] = v[4];  lh[0] = lh[4];  rh[0] = rh[4];
    v[1] = v[5];  lh[1] = lh[5];  rh[1] = rh[5];

    // ---- Chunk B: batch-load rows y0+5 .. y0+8 (4 independent LDG.128) ----
    #pragma unroll
    for (int j = 2; j < 6; j++)
        v[j] = load4<CLAMP>(p, x4, y0 + j + 3);
    #pragma unroll
    for (int j = 2; j < 6; j++)
        halo_row<CLAMP>(p, x4, y0 + j + 3, lane, v[j], lh[j], rh[j]);
    compute4(v, lh, rh, qb + 4 * WW);
}

__global__ void __launch_bounds__(TPB)
nms2d_kernel(const float* __restrict__ x, float* __restrict__ out) {
    const int img = blockIdx.z;
    const size_t base = (size_t)img * HH * WW;
    const float* __restrict__ p = x + base;
    float* __restrict__ q = out + base;

    const int lane = threadIdx.x & 31;
    const int x4 = (blockIdx.x * TPB + threadIdx.x) * 4;
    const int y0 = blockIdx.y * RPT;

    if (y0 > 0 && y0 + RPT < HH) {
        nms_tile<false>(p, q, x4, y0, lane);   // interior: no y clamps
    } else {
        nms_tile<true>(p, q, x4, y0, lane);    // top/bottom edge strips
    }
}

extern "C" void kernel_launch(void* const* d_in, const int* in_sizes, int n_in,
                              void* d_out, int out_size) {
    const float* x = (const float*)d_in[0];
    float* out = (float*)d_out;

    const int n_img = in_sizes[0] / (HH * WW);   // 32

    dim3 block(TPB, 1, 1);
    dim3 grid(WW / (TPB * 4), HH / RPT, n_img);
    nms2d_kernel<<<grid, block>>>(x, out);
}